// round 17
// baseline (speedup 1.0000x reference)
#include <cuda_runtime.h>
#include <cuda_bf16.h>
#include <cstdint>

#define S_LEN 2048
#define D_MODEL 1024
#define NH 16
#define HD 64
#define NB 2
#define NG 32
#define SN (NB * S_LEN)                 // 4096 rows of X
#define XELE (SN * D_MODEL)             // 4,194,304
#define WELE (D_MODEL * D_MODEL)        // 1,048,576
#define TOT_SPLIT (3 * XELE + 4 * WELE) // 16,777,216
#define HELE (NB * NH * S_LEN * HD)     // 4,194,304

// ---------------------------------------------------------------------------
// Scratch (device globals: no allocations allowed)
// ---------------------------------------------------------------------------
__device__ int g_isg[S_LEN];
__device__ int g_gvalid[NG];
// fragment-packed bf16 hi/lo: [q|k|v A-frags (3*XELE) | Wq..Wo B-frags (4*WELE)]
__device__ __nv_bfloat16 g_BH[TOT_SPLIT];
__device__ __nv_bfloat16 g_BL[TOT_SPLIT];
// ctx A-frags (written directly by attn epilogue; read by output projection)
__device__ __nv_bfloat16 g_CH[XELE];
__device__ __nv_bfloat16 g_CL[XELE];
// bf16 hi/lo splits of projected Q/K/V in [B,H,S,HD]
__device__ __nv_bfloat16 g_QH[HELE], g_QL[HELE];
__device__ __nv_bfloat16 g_KH[HELE], g_KL[HELE];
__device__ __nv_bfloat16 g_VH[HELE], g_VL[HELE];

// ---------------------------------------------------------------------------
__device__ __forceinline__ uint32_t smem_u32(const void* p) {
    uint32_t a;
    asm("{ .reg .u64 t; cvta.to.shared.u64 t, %1; cvt.u32.u64 %0, t; }"
        : "=r"(a) : "l"(p));
    return a;
}

#define LDM4(R, ADDR) \
    asm volatile("ldmatrix.sync.aligned.m8n8.x4.shared.b16 {%0,%1,%2,%3}, [%4];" \
        : "=r"((R)[0]), "=r"((R)[1]), "=r"((R)[2]), "=r"((R)[3]) : "r"(ADDR))

#define LDM4T(R, ADDR) \
    asm volatile("ldmatrix.sync.aligned.m8n8.x4.trans.shared.b16 {%0,%1,%2,%3}, [%4];" \
        : "=r"((R)[0]), "=r"((R)[1]), "=r"((R)[2]), "=r"((R)[3]) : "r"(ADDR))

#define MMA16816(C, A, B0, B1) \
    asm volatile("mma.sync.aligned.m16n8k16.row.col.f32.bf16.bf16.f32 " \
        "{%0,%1,%2,%3}, {%4,%5,%6,%7}, {%8,%9}, {%0,%1,%2,%3};" \
        : "+f"((C)[0]), "+f"((C)[1]), "+f"((C)[2]), "+f"((C)[3]) \
        : "r"((A)[0]), "r"((A)[1]), "r"((A)[2]), "r"((A)[3]), "r"(B0), "r"(B1))

#define MMA16816_V(C, A0, A1, A2, A3, B0, B1) \
    asm volatile("mma.sync.aligned.m16n8k16.row.col.f32.bf16.bf16.f32 " \
        "{%0,%1,%2,%3}, {%4,%5,%6,%7}, {%8,%9}, {%0,%1,%2,%3};" \
        : "+f"((C)[0]), "+f"((C)[1]), "+f"((C)[2]), "+f"((C)[3]) \
        : "r"(A0), "r"(A1), "r"(A2), "r"(A3), "r"(B0), "r"(B1))

// ---------------------------------------------------------------------------
// Flags
// ---------------------------------------------------------------------------
__global__ void flags_kernel(const int* __restrict__ gidx) {
    int t = threadIdx.x;
    for (int s = t; s < S_LEN; s += blockDim.x) g_isg[s] = 0;
    __syncthreads();
    if (t < NG) {
        int g = gidx[t];
        g_isg[g] = 1;
        int v = 1;
        for (int w = 0; w < t; ++w)
            if (gidx[w] == g) v = 0;
        g_gvalid[t] = v;
    }
}

// ---------------------------------------------------------------------------
// Fragment packing (layouts documented in R10; unchanged).
// ---------------------------------------------------------------------------
__device__ __forceinline__ uint32_t pack_pair(float a, float b,
                                              uint32_t& lo_out) {
    __nv_bfloat16 ha = __float2bfloat16(a);
    __nv_bfloat16 hb = __float2bfloat16(b);
    __nv_bfloat16 la = __float2bfloat16(a - __bfloat162float(ha));
    __nv_bfloat16 lb = __float2bfloat16(b - __bfloat162float(hb));
    uint32_t hi = ((uint32_t)*(uint16_t*)&hb << 16) | *(uint16_t*)&ha;
    lo_out = ((uint32_t)*(uint16_t*)&lb << 16) | *(uint16_t*)&la;
    return hi;
}

__global__ __launch_bounds__(256) void pack_all(
    const float* __restrict__ q, const float* __restrict__ k,
    const float* __restrict__ v, const float* __restrict__ wq,
    const float* __restrict__ wk, const float* __restrict__ wv,
    const float* __restrict__ wo)
{
    int gf = blockIdx.x * 8 + (threadIdx.x >> 5);
    int lane = threadIdx.x & 31;
    int g = lane >> 2, qd = lane & 3;
    uint32_t hi[4], lo[4];
    size_t dst;
    if (gf < 49152) {  // A-type frags: 3 modes x 16384
        int mode = gf >> 14;
        int f = gf & 16383;
        int mt = f & 3, kt = (f >> 2) & 63, rt = f >> 8;
        const float* X = (mode == 0) ? q : (mode == 1) ? k : v;
        int row0 = rt * 64 + mt * 16 + g;
        int k0 = kt * 16 + qd * 2;
        const float* r0 = X + (size_t)row0 * D_MODEL + k0;
        const float* r8 = r0 + 8 * D_MODEL;
        hi[0] = pack_pair(r0[0], r0[1], lo[0]);
        hi[1] = pack_pair(r8[0], r8[1], lo[1]);
        hi[2] = pack_pair(r0[8], r0[9], lo[2]);
        hi[3] = pack_pair(r8[8], r8[9], lo[3]);
        dst = (size_t)mode * XELE + (size_t)f * 256 + lane * 8;
    } else {           // B-type frags: 4 weights x 4096
        int bf = gf - 49152;
        int w = bf >> 12;
        int f = bf & 4095;
        int nt8 = f >> 5, ktp = f & 31;
        const float* W = (w == 0) ? wq : (w == 1) ? wk : (w == 2) ? wv : wo;
        const float* r = W + (size_t)(nt8 * 8 + g) * D_MODEL + ktp * 32 + qd * 2;
        hi[0] = pack_pair(r[0], r[1], lo[0]);
        hi[1] = pack_pair(r[8], r[9], lo[1]);
        hi[2] = pack_pair(r[16], r[17], lo[2]);
        hi[3] = pack_pair(r[24], r[25], lo[3]);
        dst = 3 * (size_t)XELE + (size_t)w * WELE + (size_t)f * 256 + lane * 8;
    }
    *(uint4*)(g_BH + dst) = make_uint4(hi[0], hi[1], hi[2], hi[3]);
    *(uint4*)(g_BL + dst) = make_uint4(lo[0], lo[1], lo[2], lo[3]);
}

// ---------------------------------------------------------------------------
// Fragment GEMM (unchanged from R10/R12).
// ---------------------------------------------------------------------------
__global__ __launch_bounds__(256, 1) void gemm_frag(
    int mode, float* __restrict__ Yout,
    const float* __restrict__ b0p, const float* __restrict__ b1p,
    const float* __restrict__ b2p)
{
    int md = (mode < 0) ? (int)blockIdx.z : 3;
    const __nv_bfloat16 *AHp, *ALp;
    const float* bias;
    if (md < 3) {
        AHp = g_BH + (size_t)md * XELE;
        ALp = g_BL + (size_t)md * XELE;
        bias = (md == 0) ? b0p : (md == 1) ? b1p : b2p;
    } else {
        AHp = g_CH; ALp = g_CL; bias = b2p;
    }
    int wsel = (md == 3) ? 3 : md;
    const __nv_bfloat16* BHp = g_BH + 3 * (size_t)XELE + (size_t)wsel * WELE;
    const __nv_bfloat16* BLp = g_BL + 3 * (size_t)XELE + (size_t)wsel * WELE;

    int tid = threadIdx.x, lane = tid & 31, wid = tid >> 5;
    int warp_m = wid & 1, warp_n = wid >> 1;
    int m0 = blockIdx.y * 128, n0 = blockIdx.x * 128;
    int rt0 = (m0 >> 6) + warp_m;
    int nt80 = (n0 >> 3) + warp_n * 4;

    const uint4* aH = (const uint4*)AHp + (size_t)rt0 * 8192 + lane;
    const uint4* aL = (const uint4*)ALp + (size_t)rt0 * 8192 + lane;
    const uint4* bH = (const uint4*)BHp + (size_t)nt80 * 1024 + lane;
    const uint4* bL = (const uint4*)BLp + (size_t)nt80 * 1024 + lane;

    float acc[4][4][4];
#pragma unroll
    for (int i = 0; i < 4; ++i)
#pragma unroll
        for (int j = 0; j < 4; ++j)
#pragma unroll
            for (int c = 0; c < 4; ++c) acc[i][j][c] = 0.f;

    for (int ktp = 0; ktp < 32; ++ktp) {
        uint4 fah[4][2], fal[4][2], fbh[4], fbl[4];
#pragma unroll
        for (int mt = 0; mt < 4; ++mt)
#pragma unroll
            for (int kk = 0; kk < 2; ++kk) {
                int kt = ktp * 2 + kk;
                fah[mt][kk] = aH[(kt * 4 + mt) * 32];
                fal[mt][kk] = aL[(kt * 4 + mt) * 32];
            }
#pragma unroll
        for (int nb = 0; nb < 4; ++nb) {
            fbh[nb] = bH[(nb * 32 + ktp) * 32];
            fbl[nb] = bL[(nb * 32 + ktp) * 32];
        }
#pragma unroll
        for (int kk = 0; kk < 2; ++kk) {
#pragma unroll
            for (int mt = 0; mt < 4; ++mt) {
                uint32_t ah0 = fah[mt][kk].x, ah1 = fah[mt][kk].y,
                         ah2 = fah[mt][kk].z, ah3 = fah[mt][kk].w;
                uint32_t al0 = fal[mt][kk].x, al1 = fal[mt][kk].y,
                         al2 = fal[mt][kk].z, al3 = fal[mt][kk].w;
#pragma unroll
                for (int nb = 0; nb < 4; ++nb) {
                    uint32_t b0 = kk ? fbh[nb].z : fbh[nb].x;
                    uint32_t b1 = kk ? fbh[nb].w : fbh[nb].y;
                    uint32_t c0 = kk ? fbl[nb].z : fbl[nb].x;
                    uint32_t c1 = kk ? fbl[nb].w : fbl[nb].y;
                    MMA16816_V(acc[mt][nb], ah0, ah1, ah2, ah3, b0, b1);
                    MMA16816_V(acc[mt][nb], ah0, ah1, ah2, ah3, c0, c1);
                    MMA16816_V(acc[mt][nb], al0, al1, al2, al3, b0, b1);
                }
            }
        }
    }

    // ---- epilogue ----
    int g = lane >> 2, c2 = (lane & 3) * 2;
#pragma unroll
    for (int mt = 0; mt < 4; ++mt) {
#pragma unroll
        for (int nb = 0; nb < 4; ++nb) {
            int m = m0 + warp_m * 64 + mt * 16 + g;
            int n = n0 + warp_n * 32 + nb * 8 + c2;
            float2 bs = *(const float2*)&bias[n];
            float2 lo = make_float2(acc[mt][nb][0] + bs.x, acc[mt][nb][1] + bs.y);
            float2 hi = make_float2(acc[mt][nb][2] + bs.x, acc[mt][nb][3] + bs.y);
            if (md == 3) {
                *(float2*)&Yout[(size_t)m * D_MODEL + n] = lo;
                *(float2*)&Yout[(size_t)(m + 8) * D_MODEL + n] = hi;
            } else {
                __nv_bfloat16* DH = (md == 0) ? g_QH : (md == 1) ? g_KH : g_VH;
                __nv_bfloat16* DL = (md == 0) ? g_QL : (md == 1) ? g_KL : g_VL;
                int hh = n >> 6, dd = n & 63;
                int b2a = m >> 11, ssa = m & (S_LEN - 1);
                int b2b = (m + 8) >> 11, ssb = (m + 8) & (S_LEN - 1);
                size_t o1 = (((size_t)b2a * NH + hh) * S_LEN + ssa) * HD + dd;
                size_t o2 = (((size_t)b2b * NH + hh) * S_LEN + ssb) * HD + dd;
                uint32_t plo, phi;
                phi = pack_pair(lo.x, lo.y, plo);
                *(uint32_t*)&DH[o1] = phi;
                *(uint32_t*)&DL[o1] = plo;
                phi = pack_pair(hi.x, hi.y, plo);
                *(uint32_t*)&DH[o2] = phi;
                *(uint32_t*)&DL[o2] = plo;
            }
        }
    }
}

// ---------------------------------------------------------------------------
// Tensor-core attention, 64-row query tiles, 512 threads (16 warps: 4m x 4n).
// bx<32: parity block (64 rows i0+2r); bx==32: global-row block (32 rows,
// duplicated into 64 slots via r&31; writes guarded to r<32).
// ---------------------------------------------------------------------------
#define OFF_QH 0
#define OFF_QL 8192
#define OFF_KH 16384
#define OFF_KL 32768
#define OFF_VH 49152
#define OFF_VL 65536
#define OFF_PH 81920
#define OFF_PL 98304
#define OFF_RS 114688
#define OFF_INV 115712
#define OFF_GS 115968
#define OFF_GV 116096
#define SMEM_ATTN 116224

__global__ __launch_bounds__(512, 1) void attn_mma(const int* __restrict__ gidx)
{
    extern __shared__ __align__(128) char sm[];
    const uint32_t smb = smem_u32(sm);
    float* rssm = (float*)(sm + OFF_RS);
    float* invsm = (float*)(sm + OFF_INV);
    int* gshs = (int*)(sm + OFF_GS);
    int* gvals = (int*)(sm + OFF_GV);

    int tid = threadIdx.x, lane = tid & 31, wid = tid >> 5;
    int warp_m = wid & 3, warp_n = wid >> 2;
    int b = blockIdx.z, h = blockIdx.y, bx = blockIdx.x;
    bool gt = (bx == 32);
    size_t hb = ((size_t)(b * NH + h)) * S_LEN * HD;

    if (tid < NG) { gshs[tid] = gidx[tid]; gvals[tid] = g_gvalid[tid]; }
    __syncthreads();

    int p = 0, rp0 = 0, i0 = 0, jps = 0, nloc = 0, ntile;
    if (gt) {
        ntile = 16;
    } else {
        p = bx & 1;
        int t2 = bx >> 1;            // 0..15
        rp0 = t2 * 64;               // first parity row of this block
        i0 = t2 * 128 + p;           // first sequence row
        jps = rp0 - 256; if (jps < 0) jps = 0;
        int jpe = rp0 + 63 + 256; if (jpe > 1023) jpe = 1023;
        nloc = (jpe - jps + 128) >> 7;
        ntile = nloc + 1;
    }

    // Q tile load (64 rows x 64 d, hi+lo); gt duplicates rows via r&31
    {
        int r = tid >> 3, uq = tid & 7;
        int irow = gt ? gshs[r & 31] : (i0 + 2 * r);
        size_t go = hb + (size_t)irow * HD + uq * 8;
        uint32_t doff = (uint32_t)r * 128u + (uint32_t)((uq ^ (r & 7)) << 4);
        *(uint4*)(sm + OFF_QH + doff) = *(const uint4*)(g_QH + go);
        *(uint4*)(sm + OFF_QL + doff) = *(const uint4*)(g_QL + go);
    }

    int g = lane >> 2, c2 = (lane & 3) * 2;
    int r1 = warp_m * 16 + g, r2 = r1 + 8;     // 0..63
    int i1 = gt ? gshs[r1 & 31] : (i0 + 2 * r1);
    int i2 = gt ? gshs[r2 & 31] : (i0 + 2 * r2);
    int lsw = lane & 7;

    float rs1 = 0.f, rs2 = 0.f;
    float oacc[2][4];
#pragma unroll
    for (int i = 0; i < 2; ++i)
#pragma unroll
        for (int j = 0; j < 4; ++j) oacc[i][j] = 0.f;

    int uld = tid & 7, rowgrp = tid >> 3;  // coalesced loader: 64 row groups

    for (int ti = 0; ti < ntile; ++ti) {
        bool gcol = (!gt) && (ti == nloc);
        __syncthreads();  // previous tile fully consumed
        // ---- K/V tile load: 8 lanes cover one 128B row contiguously ----
#pragma unroll
        for (int it = 0; it < 2; ++it) {
            int slot = rowgrp + 64 * it;
            if (gcol && slot >= 32) continue;  // gcol: rows >=32 never read
            int s = 0;
            bool valid;
            if (gt) { s = (ti << 7) + slot; valid = true; }
            else if (ti < nloc) {
                int jp = jps + (ti << 7) + slot;
                valid = jp < 1024;
                s = 2 * jp + p;
            } else {
                valid = slot < 32;
                s = valid ? gshs[slot] : 0;
            }
            size_t ro = hb + (size_t)s * HD + uld * 8;
            uint32_t off = (uint32_t)slot * 128u +
                           (uint32_t)((uld ^ (slot & 7)) << 4);
            uint4 z = make_uint4(0, 0, 0, 0);
            *(uint4*)(sm + OFF_KH + off) = valid ? *(const uint4*)(g_KH + ro) : z;
            *(uint4*)(sm + OFF_KL + off) = valid ? *(const uint4*)(g_KL + ro) : z;
            *(uint4*)(sm + OFF_VH + off) = valid ? *(const uint4*)(g_VH + ro) : z;
            *(uint4*)(sm + OFF_VL + off) = valid ? *(const uint4*)(g_VL + ro) : z;
        }
        __syncthreads();

        // ---- S = Q*K^T (3-term split) ----
        float sacc[4][4];
#pragma unroll
        for (int i = 0; i < 4; ++i)
#pragma unroll
            for (int j = 0; j < 4; ++j) sacc[i][j] = 0.f;

        if (!(gcol && warp_n > 0)) {  // gcol: only warp_n==0 has live cols
#pragma unroll
            for (int ks = 0; ks < 4; ++ks) {
                uint32_t qhf[4], qlf[4];
                {
                    int rowA = warp_m * 16 + (lane & 15);
                    uint32_t addr = smb + OFF_QH + (uint32_t)rowA * 128u +
                                    (uint32_t)((((ks * 2 + (lane >> 4)) ^ lsw) & 7) << 4);
                    LDM4(qhf, addr);
                    LDM4(qlf, addr + (OFF_QL - OFF_QH));
                }
                uint32_t khf[2][4], klf[2][4];
#pragma unroll
                for (int nb = 0; nb < 2; ++nb) {
                    int rowB = warp_n * 32 + nb * 16 + ((lane >> 4) << 3) + lsw;
                    uint32_t addr = smb + OFF_KH + (uint32_t)rowB * 128u +
                                    (uint32_t)((((ks * 2 + ((lane >> 3) & 1)) ^ lsw) & 7) << 4);
                    LDM4(khf[nb], addr);
                    LDM4(klf[nb], addr + (OFF_KL - OFF_KH));
                }
#pragma unroll
                for (int nt = 0; nt < 4; ++nt) {
                    int nb = nt >> 1, hp = (nt & 1) * 2;
                    MMA16816(sacc[nt], qhf, khf[nb][hp], khf[nb][hp + 1]);
                    MMA16816(sacc[nt], qhf, klf[nb][hp], klf[nb][hp + 1]);
                    MMA16816(sacc[nt], qlf, khf[nb][hp], khf[nb][hp + 1]);
                }
            }
        }

        // ---- mask + exp + P split store ----
#pragma unroll
        for (int nt = 0; nt < 4; ++nt) {
            int c0 = warp_n * 32 + nt * 8 + c2;
            bool ok00, ok01, ok10, ok11;
            if (gt) {
                ok00 = ok01 = ok10 = ok11 = true;
            } else if (ti < nloc) {
                int jp0 = jps + (ti << 7) + c0;
                bool j0 = jp0 < 1024, j1 = (jp0 + 1) < 1024;
                int a0 = jp0 - (rp0 + r1);
                int b0_ = jp0 - (rp0 + r2);
                ok00 = j0 && a0 >= -256 && a0 <= 256;
                ok01 = j1 && (a0 + 1) >= -256 && (a0 + 1) <= 256;
                ok10 = j0 && b0_ >= -256 && b0_ <= 256;
                ok11 = j1 && (b0_ + 1) >= -256 && (b0_ + 1) <= 256;
            } else {
                ok00 = ok01 = ok10 = ok11 = false;
                if (c0 < 32) {
                    int s0 = gshs[c0];
                    bool gv = gvals[c0] != 0;
                    int d0 = s0 - i1;
                    ok00 = gv && !(((d0 & 1) == 0) && d0 >= -512 && d0 <= 512);
                    int d2 = s0 - i2;
                    ok10 = gv && !(((d2 & 1) == 0) && d2 >= -512 && d2 <= 512);
                }
                if (c0 + 1 < 32) {
                    int s1 = gshs[c0 + 1];
                    bool gv = gvals[c0 + 1] != 0;
                    int d1 = s1 - i1;
                    ok01 = gv && !(((d1 & 1) == 0) && d1 >= -512 && d1 <= 512);
                    int d3 = s1 - i2;
                    ok11 = gv && !(((d3 & 1) == 0) && d3 >= -512 && d3 <= 512);
                }
            }
            float p00 = ok00 ? __expf(sacc[nt][0] * 0.125f) : 0.f;
            float p01 = ok01 ? __expf(sacc[nt][1] * 0.125f) : 0.f;
            float p10 = ok10 ? __expf(sacc[nt][2] * 0.125f) : 0.f;
            float p11 = ok11 ? __expf(sacc[nt][3] * 0.125f) : 0.f;
            rs1 += p00 + p01;
            rs2 += p10 + p11;

            uint32_t un = (uint32_t)(c0 >> 3);
            uint32_t inb = (uint32_t)((c0 & 7) * 2);
            {
                uint32_t u1 = (un & 8u) | ((un ^ (uint32_t)(r1 & 7)) & 7u);
                uint32_t off = (uint32_t)r1 * 256u + (u1 << 4) + inb;
                uint32_t plo, phi;
                phi = pack_pair(p00, p01, plo);
                *(uint32_t*)(sm + OFF_PH + off) = phi;
                *(uint32_t*)(sm + OFF_PL + off) = plo;
            }
            {
                uint32_t u1 = (un & 8u) | ((un ^ (uint32_t)(r2 & 7)) & 7u);
                uint32_t off = (uint32_t)r2 * 256u + (u1 << 4) + inb;
                uint32_t plo, phi;
                phi = pack_pair(p10, p11, plo);
                *(uint32_t*)(sm + OFF_PH + off) = phi;
                *(uint32_t*)(sm + OFF_PL + off) = plo;
            }
        }
        __syncthreads();

        // ---- O += P * V (3-term split, V via ldmatrix.trans) ----
        int ksN = gcol ? 2 : 8;  // gcol tile: only j<32 contribute
        for (int ks = 0; ks < ksN; ++ks) {
            uint32_t phf[4], plf[4];
            {
                int rowP = warp_m * 16 + (lane & 15);
                uint32_t un = (uint32_t)(ks * 2 + (lane >> 4));
                uint32_t u1 = (un & 8u) | ((un ^ (uint32_t)(rowP & 7)) & 7u);
                uint32_t addr = smb + OFF_PH + (uint32_t)rowP * 256u + (u1 << 4);
                LDM4(phf, addr);
                LDM4(plf, addr + (OFF_PL - OFF_PH));
            }
            uint32_t vhf[4], vlf[4];
            {
                int rowV = ks * 16 + (lane & 15);
                uint32_t un = (uint32_t)((warp_n * 2 + (lane >> 4)) ^ (rowV & 7));
                uint32_t addr = smb + OFF_VH + (uint32_t)rowV * 128u + (un << 4);
                LDM4T(vhf, addr);
                LDM4T(vlf, addr + (OFF_VL - OFF_VH));
            }
#pragma unroll
            for (int nt2 = 0; nt2 < 2; ++nt2) {
                int hp = nt2 * 2;
                MMA16816(oacc[nt2], phf, vhf[hp], vhf[hp + 1]);
                MMA16816(oacc[nt2], phf, vlf[hp], vlf[hp + 1]);
                MMA16816(oacc[nt2], plf, vhf[hp], vhf[hp + 1]);
            }
        }
    }

    // ---- rsum reduction (4 n-warp groups x 64 rows) ----
    rs1 += __shfl_xor_sync(0xffffffffu, rs1, 1);
    rs1 += __shfl_xor_sync(0xffffffffu, rs1, 2);
    rs2 += __shfl_xor_sync(0xffffffffu, rs2, 1);
    rs2 += __shfl_xor_sync(0xffffffffu, rs2, 2);
    if ((lane & 3) == 0) {
        rssm[warp_n * 64 + r1] = rs1;
        rssm[warp_n * 64 + r2] = rs2;
    }
    __syncthreads();
    if (tid < 64) {
        float t = rssm[tid] + rssm[64 + tid] + rssm[128 + tid] + rssm[192 + tid];
        invsm[tid] = 1.f / t;
    }
    __syncthreads();

    // ---- epilogue: write ctx A-fragments (hi/lo) directly ----
    float inv1 = invsm[r1], inv2 = invsm[r2];
    bool w1 = gt ? (r1 < 32) : (g_isg[i1] == 0);
    bool w2 = gt ? (r2 < 32) : (g_isg[i2] == 0);
    int m1 = b * S_LEN + i1, m2 = b * S_LEN + i2;
#pragma unroll
    for (int nt2 = 0; nt2 < 2; ++nt2) {
        int d = warp_n * 16 + nt2 * 8 + c2;
        int n = h * HD + d;
        int kt = n >> 4;
        int qd = (n >> 1) & 3;
        int half8 = (n >> 3) & 1;
        if (w1) {
            uint32_t plo, phi;
            phi = pack_pair(oacc[nt2][0] * inv1, oacc[nt2][1] * inv1, plo);
            int rt = m1 >> 6, mt = (m1 >> 4) & 3, r16 = m1 & 15;
            int lane_p = (r16 & 7) * 4 + qd;
            int reg = (r16 >> 3) + 2 * half8;
            size_t dst = ((size_t)(rt * 64 + kt) * 4 + mt) * 256 + lane_p * 8 + reg * 2;
            *(uint32_t*)(g_CH + dst) = phi;
            *(uint32_t*)(g_CL + dst) = plo;
        }
        if (w2) {
            uint32_t plo, phi;
            phi = pack_pair(oacc[nt2][2] * inv2, oacc[nt2][3] * inv2, plo);
            int rt = m2 >> 6, mt = (m2 >> 4) & 3, r16 = m2 & 15;
            int lane_p = (r16 & 7) * 4 + qd;
            int reg = (r16 >> 3) + 2 * half8;
            size_t dst = ((size_t)(rt * 64 + kt) * 4 + mt) * 256 + lane_p * 8 + reg * 2;
            *(uint32_t*)(g_CH + dst) = phi;
            *(uint32_t*)(g_CL + dst) = plo;
        }
    }
}

// ---------------------------------------------------------------------------
extern "C" void kernel_launch(void* const* d_in, const int* in_sizes, int n_in,
                              void* d_out, int out_size) {
    const float* q  = (const float*)d_in[0];
    const float* k  = (const float*)d_in[1];
    const float* v  = (const float*)d_in[2];
    const float* Wq = (const float*)d_in[3];
    const float* Wk = (const float*)d_in[4];
    const float* Wv = (const float*)d_in[5];
    const float* Wo = (const float*)d_in[6];
    const float* bq = (const float*)d_in[7];
    const float* bk = (const float*)d_in[8];
    const float* bv = (const float*)d_in[9];
    const float* bo = (const float*)d_in[10];
    const int* gidx = (const int*)d_in[11];
    float* out = (float*)d_out;

    cudaFuncSetAttribute(attn_mma, cudaFuncAttributeMaxDynamicSharedMemorySize,
                         SMEM_ATTN);

    flags_kernel<<<1, 256>>>(gidx);
    pack_all<<<8192, 256>>>(q, k, v, Wq, Wk, Wv, Wo);

    // Fused QKV projection (grid z selects Q/K/V); writes bf16 hi/lo splits.
    gemm_frag<<<dim3(D_MODEL / 128, SN / 128, 3), 256>>>(-1, nullptr, bq, bk, bv);

    // Attention writes ctx A-fragments directly (no fp32 ctx / pack pass).
    attn_mma<<<dim3(33, NH, NB), 512, SMEM_ATTN>>>(gidx);

    gemm_frag<<<dim3(D_MODEL / 128, SN / 128, 1), 256>>>(3, out, bo, bo, bo);
}